// round 16
// baseline (speedup 1.0000x reference)
#include <cuda_runtime.h>

// Model_10582799417658: 127-step LSTM-VAE rollout.
// B=4096, D=64, H=256, GATES=1024, L=64, T=128 (127 scan steps).
//
// Round 16 (base = round-15 tensor path): kill the copy-bound regression.
//  - weights stream as a SINGLE fp32 plane (1.25 MB/step, round-12 bytes);
//    tf32 hi/lo split happens in registers (bitwise-identical products).
//  - round-12 pair-ring restored: 20 sync/step, 64KB slots (2 chunks each).
//  - B fragments hoisted per-chunk (mt-invariant): 8 LDS.64 + 48 ALU/chunk.
// Phases 2a/2b/3 unchanged (round-12 verbatim).

#define B_TOT   4096
#define T_STEPS 127
#define D_IN    64
#define HID     256
#define GATE    1024
#define LAT     64
#define BT      32
#define NTH     512
#define NCTA    (B_TOT / BT)   // 128
#define MS      36             // padded m-stride (floats)
#define NPP1    20             // phase-1 pair iterations (2 chunks each)
#define NPP2    4              // phase-2 pairs (64 k each)
#define SLOT1P  16384          // phase-1 pair-slot stride (floats, 64KB)
#define SLOT2P  8192           // phase-2 slot stride (floats, 32KB)

// ---- output layout ----
#define N_STATES ((unsigned long long)B_TOT * T_STEPS * D_IN)
#define N_GENS   ((unsigned long long)B_TOT * T_STEPS)
#define N_TOTS   ((unsigned long long)B_TOT * 128)
#define O_STATES 0ULL
#define O_GENS   (O_STATES + N_STATES)
#define O_ONOFF  (O_GENS + N_GENS)
#define O_TPRE   (O_ONOFF + N_GENS)
#define O_TPOST  (O_TPRE + N_TOTS)

typedef unsigned long long ull;

__device__ float g_wgv[HID];
__device__ float g_wov[HID];
__device__ float g_b2[2];
// Phase-1 weights, SINGLE fp32 plane, fragment-interleaved:
//   chunk kc (0..39) holds k in [kc*8, kc*8+8); 8192 floats per chunk:
//   flat i: kc=i>>13, r=i&8191, comp=r&1, f2=r>>1, p=f2&3, n=f2>>2,
//           k=kc*8+p+comp*4
//   value = raw fp32 (k<64 ? Wih[n][k] : Whh[n][k-64]); runtime tf32-splits.
__device__ float g_Wt1[40 * 8192];
// Phase-2: g_Wt2[k][r] = (r<64 ? Wmu[r][k] : Wvar[r-64][k])
__device__ float g_Wt2[256 * 128];

__device__ __forceinline__ ull pack2s(float a) {   // splat (a, a)
    ull r;
    asm("mov.b64 %0, {%1,%1};" : "=l"(r) : "r"(__float_as_uint(a)));
    return r;
}
__device__ __forceinline__ void fma2(ull &d, ull a, ull b) {
    asm("fma.rn.f32x2 %0, %1, %2, %0;" : "+l"(d) : "l"(a), "l"(b));
}
__device__ __forceinline__ float2 unpack2(ull v) {
    unsigned int lo, hi;
    asm("mov.b64 {%0,%1}, %2;" : "=r"(lo), "=r"(hi) : "l"(v));
    float2 f; f.x = __uint_as_float(lo); f.y = __uint_as_float(hi);
    return f;
}
__device__ __forceinline__ float sig_f(float x) {
    return 1.0f / (1.0f + __expf(-x));
}
__device__ __forceinline__ float tanh_f(float x) {
    return 1.0f - 2.0f / (__expf(2.0f * x) + 1.0f);
}
__device__ __forceinline__ float tf32r(float x) {   // round-to-nearest tf32
    unsigned int r;
    asm("cvt.rna.tf32.f32 %0, %1;" : "=r"(r) : "f"(x));
    return __uint_as_float(r);
}
__device__ __forceinline__ void mma_tf32(float* d, const float* a, float2 b) {
    asm volatile(
        "mma.sync.aligned.m16n8k8.row.col.f32.tf32.tf32.f32 "
        "{%0,%1,%2,%3}, {%4,%5,%6,%7}, {%8,%9}, {%0,%1,%2,%3};"
        : "+f"(d[0]), "+f"(d[1]), "+f"(d[2]), "+f"(d[3])
        : "r"(__float_as_uint(a[0])), "r"(__float_as_uint(a[1])),
          "r"(__float_as_uint(a[2])), "r"(__float_as_uint(a[3])),
          "r"(__float_as_uint(b.x)),  "r"(__float_as_uint(b.y)));
}
__device__ __forceinline__ void cpa16(unsigned int dst, const void* src) {
    asm volatile("cp.async.cg.shared.global [%0], [%1], 16;" :: "r"(dst), "l"(src));
}
__device__ __forceinline__ void cpa_commit() {
    asm volatile("cp.async.commit_group;");
}
__device__ __forceinline__ void cpa_wait0() {
    asm volatile("cp.async.wait_group 0;");
}

// Merged one-time prep: rank-1 head folds + weight transforms.
__global__ void prep_all_kernel(const float* __restrict__ Wih, const float* __restrict__ Whh,
                                const float* __restrict__ Wmu, const float* __restrict__ Wvar,
                                const float* __restrict__ Wgen, const float* __restrict__ bgen,
                                const float* __restrict__ Won,  const float* __restrict__ bon,
                                const float* __restrict__ Wvelo, const float* __restrict__ bvelo,
                                const float* __restrict__ Wsw,  const float* __restrict__ bsw) {
    const int stride = gridDim.x * blockDim.x;
    const int idx = blockIdx.x * blockDim.x + threadIdx.x;

    if (blockIdx.x == 0 && threadIdx.x < HID) {
        int k = threadIdx.x;
        float s1 = 0.f, s2 = 0.f;
        #pragma unroll 4
        for (int l = 0; l < LAT; ++l) {
            s1 += Wgen[l] * Wvelo[l * HID + k];
            s2 += Won[l]  * Wsw[l * HID + k];
        }
        g_wgv[k] = s1;
        g_wov[k] = s2;
        if (k == 0) {
            float b1 = bgen[0], b2 = bon[0];
            for (int l = 0; l < LAT; ++l) {
                b1 += Wgen[l] * bvelo[l];
                b2 += Won[l]  * bsw[l];
            }
            g_b2[0] = b1; g_b2[1] = b2;
        }
    }

    for (int i = idx; i < 40 * 8192; i += stride) {
        int kc = i >> 13, r = i & 8191;
        int comp = r & 1, f2 = r >> 1;
        int p_ = f2 & 3, n = f2 >> 2;
        int k = kc * 8 + p_ + comp * 4;
        g_Wt1[i] = (k < 64) ? Wih[n * D_IN + k] : Whh[n * HID + (k - 64)];
    }
    for (int i = idx; i < 256 * 128; i += stride) {
        int k = i >> 7, r = i & 127;
        g_Wt2[i] = (r < 64) ? Wmu[r * HID + k] : Wvar[(r - 64) * HID + k];
    }
}

__global__ void __launch_bounds__(NTH, 1)
model_kernel(const float* __restrict__ data, const float* __restrict__ locs,
             const float* __restrict__ bih,  const float* __restrict__ bhh,
             const float* __restrict__ bmu,  const float* __restrict__ bvar,
             const float* __restrict__ Wnext, const float* __restrict__ bnext,
             const float* __restrict__ Wloc, const float* __restrict__ bloc,
             const float* __restrict__ eps,  float* __restrict__ out) {
    extern __shared__ float sm[];
    float* xs     = sm;                  // [64][MS]
    float* hs     = xs     + 2304;       // [256][MS]  in-place h
    float* zs     = hs     + 9216;       // [64][MS]
    float* bsum   = zs     + 2304;       // [1024]
    float* wgv    = bsum   + 1024;       // [256]
    float* wov    = wgv    + 256;        // [256]
    float* bmu_s  = wov    + 256;        // [64]
    float* bvar_s = bmu_s  + 64;         // [64]
    float* bnx_s  = bvar_s + 64;         // [64]
    float* wnT    = bnx_s  + 64;         // [64][64]
    float* abuf   = wnT    + 4096;       // [32]
    float* wbA    = abuf   + 32;         // panel area: 2 x SLOT1P (32768 floats)
    float* mus    = wbA;                 // [64][MS]  (reuse after phase 2a)
    float* lvs    = wbA + 2304;          // [64][MS]

    const unsigned int wb_u32 =
        (unsigned int)__cvta_generic_to_shared(wbA);

    const int tid   = threadIdx.x;
    const int bBase = blockIdx.x * BT;
    const int wrp = tid >> 5, lane = tid & 31;
    const int qg = lane >> 2;            // mma group id (0..7)
    const int tq = lane & 3;             // thread-in-group (0..3)
    // phase-2a tile: 8 m-tiles of 4 x 64 row-pairs
    const int m08 = (tid & 7) * 4;
    const int jq2 = (tid >> 3) * 2;      // 0..126

    // ---------------- init ----------------
    for (int i = tid; i < D_IN * BT; i += NTH) {
        int k = i / BT, m = i % BT;
        xs[k * MS + m] = data[(size_t)(bBase + m) * (128 * D_IN) + k];
    }
    for (int i = tid; i < HID * BT; i += NTH) {
        int j = i / BT, m = i % BT;
        int b = bBase + m;
        hs[j * MS + m] = locs[b * 2] * Wloc[j * 2] + locs[b * 2 + 1] * Wloc[j * 2 + 1] + bloc[j];
    }
    for (int i = tid; i < GATE; i += NTH) bsum[i] = bih[i] + bhh[i];
    for (int i = tid; i < HID; i += NTH) { wgv[i] = g_wgv[i]; wov[i] = g_wov[i]; }
    for (int i = tid; i < LAT; i += NTH) { bmu_s[i] = bmu[i]; bvar_s[i] = bvar[i]; }
    for (int i = tid; i < D_IN; i += NTH) bnx_s[i] = bnext[i];
    for (int i = tid; i < LAT * D_IN; i += NTH) {   // wnT[l][c] = Wnext[c][l]
        int l = i >> 6, c = i & 63;
        wnT[i] = Wnext[c * LAT + l];
    }
    if (tid < BT) {
        out[O_TPRE  + (size_t)(bBase + tid) * 128] = 0.f;
        out[O_TPOST + (size_t)(bBase + tid) * 128] = 0.f;
    }
    const float bgv = g_b2[0], bov = g_b2[1];

    // c state in registers: thread owns, per (s,mt,rh), the j-pair
    // j0 = wrp*16 + s*8 + tq*2 at row m = mt*16 + qg + rh*8.
    float c_reg[16];
    #pragma unroll
    for (int i = 0; i < 16; ++i) c_reg[i] = 0.f;
    __syncthreads();

    // panel issue helpers (cp.async, 16B granules)
    auto issue1 = [&](int pp, int slot) {   // 16384 floats = 8 x 512 float4
        const float4* src = ((const float4*)g_Wt1) + (size_t)pp * 4096 + tid;
        unsigned int dst = wb_u32 + (unsigned int)slot * (SLOT1P * 4u) + tid * 16u;
        #pragma unroll
        for (int i = 0; i < 8; ++i)
            cpa16(dst + (unsigned int)i * 8192u, src + i * 512);
    };
    auto issue2 = [&](int pp, int slot) {   // 8192 floats = 4 x 512 float4
        const float4* src = ((const float4*)g_Wt2) + (size_t)pp * 2048 + tid;
        unsigned int dst = wb_u32 + (unsigned int)slot * (SLOT2P * 4u) + tid * 16u;
        #pragma unroll
        for (int i = 0; i < 4; ++i)
            cpa16(dst + (unsigned int)i * 8192u, src + i * 512);
    };

    for (int t = 0; t < T_STEPS; ++t) {
        // prefetch eps for phase 2b
        float ea[2], eb[2];
        {
            const int mr = wrp * 2;
            const float* ep = eps + ((size_t)t * B_TOT + bBase + mr) * LAT;
            ea[0] = __ldg(ep + lane);        eb[0] = __ldg(ep + lane + 32);
            ea[1] = __ldg(ep + LAT + lane);  eb[1] = __ldg(ep + LAT + lane + 32);
        }

        // ======== Phase 1: gates GEMM via 3xTF32 mma, LSTM update ========
        {
            issue1(0, 0); cpa_commit();

            float dacc[2][8][4];
            #pragma unroll
            for (int a = 0; a < 2; ++a)
                #pragma unroll
                for (int b = 0; b < 8; ++b)
                    #pragma unroll
                    for (int c = 0; c < 4; ++c) dacc[a][b][c] = 0.f;

            for (int pp = 0; pp < NPP1; ++pp) {
                cpa_wait0();         // pair pp arrived
                __syncthreads();     // visible to all; pair pp-1 fully consumed
                if (pp + 1 < NPP1) { issue1(pp + 1, (pp + 1) & 1); cpa_commit(); }
                #pragma unroll
                for (int ck = 0; ck < 2; ++ck) {
                    const int chunk = pp * 2 + ck;
                    const float* wc = wbA + (pp & 1) * SLOT1P + ck * 8192;
                    const float* Ab = (chunk < 8) ? (xs + chunk * 8 * MS)
                                                  : (hs + (chunk * 8 - 64) * MS);
                    // B fragments for all 8 n-tiles (mt-invariant), runtime split
                    float2 BH2[8], BL2[8];
                    #pragma unroll
                    for (int nf = 0; nf < 8; ++nf) {
                        int g = nf >> 1, s = nf & 1;
                        int n = (g << 8) + wrp * 16 + (s << 3) + qg;
                        float2 w = *((const float2*)wc + n * 4 + tq);
                        float hx = tf32r(w.x), hy = tf32r(w.y);
                        BH2[nf].x = hx; BL2[nf].x = tf32r(w.x - hx);
                        BH2[nf].y = hy; BL2[nf].y = tf32r(w.y - hy);
                    }
                    #pragma unroll
                    for (int mt = 0; mt < 2; ++mt) {
                        float ah[4], al[4];
                        #pragma unroll
                        for (int r = 0; r < 4; ++r) {
                            int c = ((r >> 1) << 2) + tq;          // k in chunk
                            int m = mt * 16 + qg + ((r & 1) << 3); // batch row
                            float a = Ab[c * MS + m];
                            ah[r] = tf32r(a);
                            al[r] = tf32r(a - ah[r]);
                        }
                        #pragma unroll
                        for (int nf = 0; nf < 8; ++nf) {
                            float* D = dacc[mt][nf];
                            mma_tf32(D, ah, BH2[nf]);
                            mma_tf32(D, ah, BL2[nf]);
                            mma_tf32(D, al, BH2[nf]);
                        }
                    }
                }
            }
            __syncthreads();         // all warps done reading hs/panels

            // epilogue: bias + LSTM nonlinearity; c in regs, h in place
            #pragma unroll
            for (int s = 0; s < 2; ++s) {
                const int j0 = wrp * 16 + (s << 3) + (tq << 1);
                const int j1 = j0 + 1;
                const float bi0 = bsum[j0],       bi1 = bsum[j1];
                const float bf0 = bsum[256 + j0], bf1 = bsum[256 + j1];
                const float bg0 = bsum[512 + j0], bg1 = bsum[512 + j1];
                const float bo0 = bsum[768 + j0], bo1 = bsum[768 + j1];
                #pragma unroll
                for (int mt = 0; mt < 2; ++mt) {
                    #pragma unroll
                    for (int rh = 0; rh < 2; ++rh) {
                        const int m = mt * 16 + qg + (rh << 3);
                        const int cb = ((((s << 1) | mt) << 1) | rh) << 1;
                        {
                            float iv = sig_f(dacc[mt][0 + s][rh * 2] + bi0);
                            float fv = sig_f(dacc[mt][2 + s][rh * 2] + bf0);
                            float gv = tanh_f(dacc[mt][4 + s][rh * 2] + bg0);
                            float ov = sig_f(dacc[mt][6 + s][rh * 2] + bo0);
                            float c = fv * c_reg[cb] + iv * gv;
                            c_reg[cb] = c;
                            hs[j0 * MS + m] = ov * tanh_f(c);
                        }
                        {
                            float iv = sig_f(dacc[mt][0 + s][rh * 2 + 1] + bi1);
                            float fv = sig_f(dacc[mt][2 + s][rh * 2 + 1] + bf1);
                            float gv = tanh_f(dacc[mt][4 + s][rh * 2 + 1] + bg1);
                            float ov = sig_f(dacc[mt][6 + s][rh * 2 + 1] + bo1);
                            float c = fv * c_reg[cb + 1] + iv * gv;
                            c_reg[cb + 1] = c;
                            hs[j1 * MS + m] = ov * tanh_f(c);
                        }
                    }
                }
            }
        }

        // ======== Phase 2a: [mu;logvar] = h @ [Wmu;Wvar]^T (FFMA2) ========
        {
            issue2(0, 0); cpa_commit();

            ull acc2[4] = {0ULL, 0ULL, 0ULL, 0ULL};

            for (int pp = 0; pp < NPP2; ++pp) {
                cpa_wait0();
                __syncthreads();     // also orders phase-1 hs epilogue writes
                if (pp + 1 < NPP2) { issue2(pp + 1, (pp + 1) & 1); cpa_commit(); }
                const float* wc = wbA + (pp & 1) * SLOT2P;
                const int k0 = pp * 64;
                #pragma unroll 16
                for (int kk = 0; kk < 64; ++kk) {
                    float4 a = *(const float4*)(hs + (k0 + kk) * MS + m08);
                    ull w = *(const ull*)(wc + kk * 128 + jq2);
                    fma2(acc2[0], pack2s(a.x), w);
                    fma2(acc2[1], pack2s(a.y), w);
                    fma2(acc2[2], pack2s(a.z), w);
                    fma2(acc2[3], pack2s(a.w), w);
                }
            }
            __syncthreads();         // all warps done with panel slots

            // epilogue: row pair (jq2, jq2+1) for 4 m rows -> mus/lvs (slot0)
            if (jq2 < 64) {
                const float b0 = bmu_s[jq2], b1 = bmu_s[jq2 + 1];
                #pragma unroll
                for (int m = 0; m < 4; ++m) {
                    float2 v = unpack2(acc2[m]);
                    mus[jq2 * MS + m08 + m]       = v.x + b0;
                    mus[(jq2 + 1) * MS + m08 + m] = v.y + b1;
                }
            } else {
                const int l0 = jq2 - 64;
                const float b0 = bvar_s[l0], b1 = bvar_s[l0 + 1];
                #pragma unroll
                for (int m = 0; m < 4; ++m) {
                    float2 v = unpack2(acc2[m]);
                    lvs[l0 * MS + m08 + m]       = v.x + b0;
                    lvs[(l0 + 1) * MS + m08 + m] = v.y + b1;
                }
            }
        }
        __syncthreads();

        // ======== Phase 2b: gen/on + reparameterized z ========
        #pragma unroll
        for (int r = 0; r < 2; ++r) {
            const int m = wrp * 2 + r;
            const int b = bBase + m;
            float gp = 0.f, op = 0.f;
            #pragma unroll
            for (int i2 = 0; i2 < 8; ++i2) {
                int k = lane + 32 * i2;
                float hv = hs[k * MS + m];
                gp = fmaf(hv, wgv[k], gp);
                op = fmaf(hv, wov[k], op);
            }
            #pragma unroll
            for (int s2 = 16; s2 > 0; s2 >>= 1) {
                gp += __shfl_xor_sync(0xffffffffu, gp, s2);
                op += __shfl_xor_sync(0xffffffffu, op, s2);
            }
            if (lane == 0) {
                float gen = fmaxf(gp + bgv, 0.f);
                float on  = (op + bov) > 0.f ? 1.f : 0.f;
                abuf[m] = gen * on;
                out[O_GENS  + (size_t)b * T_STEPS + t] = gen;
                out[O_ONOFF + (size_t)b * T_STEPS + t] = on;
            }
            float mu0 = mus[lane * MS + m],        lv0 = lvs[lane * MS + m];
            float mu1 = mus[(lane + 32) * MS + m], lv1 = lvs[(lane + 32) * MS + m];
            zs[lane * MS + m]        = ea[r] * __expf(0.5f * lv0) + mu0;
            zs[(lane + 32) * MS + m] = eb[r] * __expf(0.5f * lv1) + mu1;
        }
        __syncwarp();

        // ======== Phase 3: delta = z@Wnext^T, state update, totals ========
        #pragma unroll
        for (int r = 0; r < 2; ++r) {
            const int m = wrp * 2 + r;
            const int b = bBase + m;
            float d0 = bnx_s[lane], d1 = bnx_s[lane + 32];
            #pragma unroll 8
            for (int l = 0; l < LAT; ++l) {
                float zl = zs[l * MS + m];
                d0 = fmaf(zl, wnT[l * 64 + lane],      d0);
                d1 = fmaf(zl, wnT[l * 64 + lane + 32], d1);
            }
            float xn0 = (lane == 0) ? 0.f : fmaxf(xs[lane * MS + m] + d0, 0.f);
            float xn1 = fmaxf(xs[(lane + 32) * MS + m] + d1, 0.f);
            float part = xn0 + xn1;
            #pragma unroll
            for (int s2 = 16; s2 > 0; s2 >>= 1)
                part += __shfl_xor_sync(0xffffffffu, part, s2);
            float add = abuf[m];
            float v0 = (lane == 0) ? add : xn0;
            size_t ob = O_STATES + ((size_t)b * T_STEPS + t) * D_IN;
            out[ob + lane]      = v0;
            out[ob + lane + 32] = xn1;
            xs[lane * MS + m]        = v0;
            xs[(lane + 32) * MS + m] = xn1;
            if (lane == 0) {
                out[O_TPRE  + (size_t)b * 128 + t + 1] = part;
                out[O_TPOST + (size_t)b * 128 + t + 1] = part + add;
            }
        }
        __syncthreads();   // xs/hs stable before next step's phase 1
    }
}

extern "C" void kernel_launch(void* const* d_in, const int* in_sizes, int n_in,
                              void* d_out, int out_size) {
    const float* data  = (const float*)d_in[0];
    const float* locs  = (const float*)d_in[1];
    const float* Wih   = (const float*)d_in[2];
    const float* Whh   = (const float*)d_in[3];
    const float* bih   = (const float*)d_in[4];
    const float* bhh   = (const float*)d_in[5];
    const float* Wmu   = (const float*)d_in[6];
    const float* bmu   = (const float*)d_in[7];
    const float* Wvar  = (const float*)d_in[8];
    const float* bvar  = (const float*)d_in[9];
    const float* Wvelo = (const float*)d_in[10];
    const float* bvelo = (const float*)d_in[11];
    const float* Wsw   = (const float*)d_in[12];
    const float* bsw   = (const float*)d_in[13];
    const float* Wgen  = (const float*)d_in[14];
    const float* bgen  = (const float*)d_in[15];
    const float* Won   = (const float*)d_in[16];
    const float* bon   = (const float*)d_in[17];
    const float* Wnext = (const float*)d_in[18];
    const float* bnext = (const float*)d_in[19];
    const float* Wloc  = (const float*)d_in[20];
    const float* bloc  = (const float*)d_in[21];
    const float* eps   = (const float*)d_in[22];
    float* out = (float*)d_out;

    prep_all_kernel<<<256, 512>>>(Wih, Whh, Wmu, Wvar,
                                  Wgen, bgen, Won, bon,
                                  Wvelo, bvelo, Wsw, bsw);

    // floats: 19680 (state) + 2 * 16384 (pair slots) = 52448
    const size_t smem_bytes = 52448 * sizeof(float);  // 209,792 B
    cudaFuncSetAttribute(model_kernel,
                         cudaFuncAttributeMaxDynamicSharedMemorySize,
                         (int)smem_bytes);
    model_kernel<<<NCTA, NTH, smem_bytes>>>(data, locs, bih, bhh,
                                            bmu, bvar, Wnext, bnext,
                                            Wloc, bloc, eps, out);
}

// round 17
// speedup vs baseline: 1.1268x; 1.1268x over previous
#include <cuda_runtime.h>

// Model_10582799417658: 127-step LSTM-VAE rollout.
// B=4096, D=64, H=256, GATES=1024, L=64, T=128 (127 scan steps).
//
// Round 17 (base = round-15 tensor path, 9344us):
//  - B-lo plane compressed to bf16 (unpack = 2 LOP ops, no cvt chains;
//    weight repr error 2^-19 -> rel_err stays ~5e-6). Chunk 64KB -> 48KB.
//  - 3-slot cp.async ring, wait_group 1 (2 panels in flight): per-panel copy
//    latency hidden (round 15 was depth-1 and copy-exposed 40x/step).
//  - B-hi stays prep-split tf32 (no runtime ALU); A-split runtime (proven).
// Phases 2a/2b/3 round-15 verbatim.

#define B_TOT   4096
#define T_STEPS 127
#define D_IN    64
#define HID     256
#define GATE    1024
#define LAT     64
#define BT      32
#define NTH     512
#define NCTA    (B_TOT / BT)   // 128
#define MS      36             // padded m-stride (floats)
#define NP1     40             // phase-1 chunks (8 k each)
#define NPP2    4              // phase-2 pairs (64 k each)
#define SLOTC   12288          // phase-1 slot stride: hi 8192 f + lo 4096 u32
#define SLOT2P  8192           // phase-2 slot stride (floats, 32KB)

// ---- output layout ----
#define N_STATES ((unsigned long long)B_TOT * T_STEPS * D_IN)
#define N_GENS   ((unsigned long long)B_TOT * T_STEPS)
#define N_TOTS   ((unsigned long long)B_TOT * 128)
#define O_STATES 0ULL
#define O_GENS   (O_STATES + N_STATES)
#define O_ONOFF  (O_GENS + N_GENS)
#define O_TPRE   (O_ONOFF + N_GENS)
#define O_TPOST  (O_TPRE + N_TOTS)

typedef unsigned long long ull;

__device__ float g_wgv[HID];
__device__ float g_wov[HID];
__device__ float g_b2[2];
// Phase-1 weights, fragment-interleaved (chunk kc holds k in [kc*8, kc*8+8)):
//  hi plane (fp32, tf32-rounded): flat i: kc=i>>13, r=i&8191, comp=r&1,
//    f2=r>>1, p=f2&3, n=f2>>2, k=kc*8+p+comp*4; value = tf32(W[n][k]).
//  lo plane (bf16x2 packed in u32): flat i: kc=i>>12, j=i&4095, p=j&3, n=j>>2;
//    u = bf16(W[n][kc*8+p]-hi) | bf16(W[n][kc*8+p+4]-hi')<<16.
//  W row n: k<64 -> Wih[n][k], else Whh[n][k-64].
__device__ float    g_Wt1h[40 * 8192];
__device__ unsigned g_Wt1l[40 * 4096];
// Phase-2: g_Wt2[k][r] = (r<64 ? Wmu[r][k] : Wvar[r-64][k])
__device__ float g_Wt2[256 * 128];

__device__ __forceinline__ ull pack2s(float a) {   // splat (a, a)
    ull r;
    asm("mov.b64 %0, {%1,%1};" : "=l"(r) : "r"(__float_as_uint(a)));
    return r;
}
__device__ __forceinline__ void fma2(ull &d, ull a, ull b) {
    asm("fma.rn.f32x2 %0, %1, %2, %0;" : "+l"(d) : "l"(a), "l"(b));
}
__device__ __forceinline__ float2 unpack2(ull v) {
    unsigned int lo, hi;
    asm("mov.b64 {%0,%1}, %2;" : "=r"(lo), "=r"(hi) : "l"(v));
    float2 f; f.x = __uint_as_float(lo); f.y = __uint_as_float(hi);
    return f;
}
__device__ __forceinline__ float sig_f(float x) {
    return 1.0f / (1.0f + __expf(-x));
}
__device__ __forceinline__ float tanh_f(float x) {
    return 1.0f - 2.0f / (__expf(2.0f * x) + 1.0f);
}
__device__ __forceinline__ float tf32r(float x) {   // round-to-nearest tf32
    unsigned int r;
    asm("cvt.rna.tf32.f32 %0, %1;" : "=r"(r) : "f"(x));
    return __uint_as_float(r);
}
__device__ __forceinline__ unsigned bf16_rne(float x) {
    unsigned b = __float_as_uint(x);
    return (b + 0x7FFFu + ((b >> 16) & 1u)) >> 16;
}
__device__ __forceinline__ void mma_tf32(float* d, const float* a, float2 b) {
    asm volatile(
        "mma.sync.aligned.m16n8k8.row.col.f32.tf32.tf32.f32 "
        "{%0,%1,%2,%3}, {%4,%5,%6,%7}, {%8,%9}, {%0,%1,%2,%3};"
        : "+f"(d[0]), "+f"(d[1]), "+f"(d[2]), "+f"(d[3])
        : "r"(__float_as_uint(a[0])), "r"(__float_as_uint(a[1])),
          "r"(__float_as_uint(a[2])), "r"(__float_as_uint(a[3])),
          "r"(__float_as_uint(b.x)),  "r"(__float_as_uint(b.y)));
}
__device__ __forceinline__ void cpa16(unsigned int dst, const void* src) {
    asm volatile("cp.async.cg.shared.global [%0], [%1], 16;" :: "r"(dst), "l"(src));
}
__device__ __forceinline__ void cpa_commit() {
    asm volatile("cp.async.commit_group;");
}
__device__ __forceinline__ void cpa_wait0() {
    asm volatile("cp.async.wait_group 0;");
}
__device__ __forceinline__ void cpa_wait1() {
    asm volatile("cp.async.wait_group 1;");
}

// Merged one-time prep: rank-1 head folds + weight transforms.
__global__ void prep_all_kernel(const float* __restrict__ Wih, const float* __restrict__ Whh,
                                const float* __restrict__ Wmu, const float* __restrict__ Wvar,
                                const float* __restrict__ Wgen, const float* __restrict__ bgen,
                                const float* __restrict__ Won,  const float* __restrict__ bon,
                                const float* __restrict__ Wvelo, const float* __restrict__ bvelo,
                                const float* __restrict__ Wsw,  const float* __restrict__ bsw) {
    const int stride = gridDim.x * blockDim.x;
    const int idx = blockIdx.x * blockDim.x + threadIdx.x;

    if (blockIdx.x == 0 && threadIdx.x < HID) {
        int k = threadIdx.x;
        float s1 = 0.f, s2 = 0.f;
        #pragma unroll 4
        for (int l = 0; l < LAT; ++l) {
            s1 += Wgen[l] * Wvelo[l * HID + k];
            s2 += Won[l]  * Wsw[l * HID + k];
        }
        g_wgv[k] = s1;
        g_wov[k] = s2;
        if (k == 0) {
            float b1 = bgen[0], b2 = bon[0];
            for (int l = 0; l < LAT; ++l) {
                b1 += Wgen[l] * bvelo[l];
                b2 += Won[l]  * bsw[l];
            }
            g_b2[0] = b1; g_b2[1] = b2;
        }
    }

    for (int i = idx; i < 40 * 8192; i += stride) {
        int kc = i >> 13, r = i & 8191;
        int comp = r & 1, f2 = r >> 1;
        int p_ = f2 & 3, n = f2 >> 2;
        int k = kc * 8 + p_ + comp * 4;
        float w = (k < 64) ? Wih[n * D_IN + k] : Whh[n * HID + (k - 64)];
        g_Wt1h[i] = tf32r(w);
    }
    for (int i = idx; i < 40 * 4096; i += stride) {
        int kc = i >> 12, j = i & 4095;
        int p_ = j & 3, n = j >> 2;
        int k0 = kc * 8 + p_, k1 = k0 + 4;
        float w0 = (k0 < 64) ? Wih[n * D_IN + k0] : Whh[n * HID + (k0 - 64)];
        float w1 = (k1 < 64) ? Wih[n * D_IN + k1] : Whh[n * HID + (k1 - 64)];
        float l0 = w0 - tf32r(w0);
        float l1 = w1 - tf32r(w1);
        g_Wt1l[i] = bf16_rne(l0) | (bf16_rne(l1) << 16);
    }
    for (int i = idx; i < 256 * 128; i += stride) {
        int k = i >> 7, r = i & 127;
        g_Wt2[i] = (r < 64) ? Wmu[r * HID + k] : Wvar[(r - 64) * HID + k];
    }
}

__global__ void __launch_bounds__(NTH, 1)
model_kernel(const float* __restrict__ data, const float* __restrict__ locs,
             const float* __restrict__ bih,  const float* __restrict__ bhh,
             const float* __restrict__ bmu,  const float* __restrict__ bvar,
             const float* __restrict__ Wnext, const float* __restrict__ bnext,
             const float* __restrict__ Wloc, const float* __restrict__ bloc,
             const float* __restrict__ eps,  float* __restrict__ out) {
    extern __shared__ float sm[];
    float* xs     = sm;                  // [64][MS]
    float* hs     = xs     + 2304;       // [256][MS]  in-place h
    float* zs     = hs     + 9216;       // [64][MS]
    float* bsum   = zs     + 2304;       // [1024]
    float* wgv    = bsum   + 1024;       // [256]
    float* wov    = wgv    + 256;        // [256]
    float* bmu_s  = wov    + 256;        // [64]
    float* bvar_s = bmu_s  + 64;         // [64]
    float* bnx_s  = bvar_s + 64;         // [64]
    float* wnT    = bnx_s  + 64;         // [64][64]
    float* abuf   = wnT    + 4096;       // [32]
    float* wbA    = abuf   + 32;         // panel area: 3 x SLOTC (36864 floats)
    float* mus    = wbA;                 // [64][MS]  (reuse after phase 2a)
    float* lvs    = wbA + 2304;          // [64][MS]

    const unsigned int wb_u32 =
        (unsigned int)__cvta_generic_to_shared(wbA);

    const int tid   = threadIdx.x;
    const int bBase = blockIdx.x * BT;
    const int wrp = tid >> 5, lane = tid & 31;
    const int qg = lane >> 2;            // mma group id (0..7)
    const int tq = lane & 3;             // thread-in-group (0..3)
    // phase-2a tile: 8 m-tiles of 4 x 64 row-pairs
    const int m08 = (tid & 7) * 4;
    const int jq2 = (tid >> 3) * 2;      // 0..126

    // ---------------- init ----------------
    for (int i = tid; i < D_IN * BT; i += NTH) {
        int k = i / BT, m = i % BT;
        xs[k * MS + m] = data[(size_t)(bBase + m) * (128 * D_IN) + k];
    }
    for (int i = tid; i < HID * BT; i += NTH) {
        int j = i / BT, m = i % BT;
        int b = bBase + m;
        hs[j * MS + m] = locs[b * 2] * Wloc[j * 2] + locs[b * 2 + 1] * Wloc[j * 2 + 1] + bloc[j];
    }
    for (int i = tid; i < GATE; i += NTH) bsum[i] = bih[i] + bhh[i];
    for (int i = tid; i < HID; i += NTH) { wgv[i] = g_wgv[i]; wov[i] = g_wov[i]; }
    for (int i = tid; i < LAT; i += NTH) { bmu_s[i] = bmu[i]; bvar_s[i] = bvar[i]; }
    for (int i = tid; i < D_IN; i += NTH) bnx_s[i] = bnext[i];
    for (int i = tid; i < LAT * D_IN; i += NTH) {   // wnT[l][c] = Wnext[c][l]
        int l = i >> 6, c = i & 63;
        wnT[i] = Wnext[c * LAT + l];
    }
    if (tid < BT) {
        out[O_TPRE  + (size_t)(bBase + tid) * 128] = 0.f;
        out[O_TPOST + (size_t)(bBase + tid) * 128] = 0.f;
    }
    const float bgv = g_b2[0], bov = g_b2[1];

    // c state in registers: thread owns, per (s,mt,rh), the j-pair
    // j0 = wrp*16 + s*8 + tq*2 at row m = mt*16 + qg + rh*8.
    float c_reg[16];
    #pragma unroll
    for (int i = 0; i < 16; ++i) c_reg[i] = 0.f;
    __syncthreads();

    // panel issue helpers (cp.async, 16B granules)
    auto issue1 = [&](int p, int slot) {
        // hi: 8192 floats = 4 x 512 float4; lo: 4096 u32 = 2 x 512 float4
        const float4* srh = ((const float4*)g_Wt1h) + (size_t)p * 2048 + tid;
        const float4* srl = ((const float4*)g_Wt1l) + (size_t)p * 1024 + tid;
        unsigned int base = wb_u32 + (unsigned int)slot * (SLOTC * 4u);
        unsigned int dh = base + tid * 16u;
        cpa16(dh,           srh);
        cpa16(dh + 8192u,   srh + 512);
        cpa16(dh + 16384u,  srh + 1024);
        cpa16(dh + 24576u,  srh + 1536);
        unsigned int dl = base + 32768u + tid * 16u;
        cpa16(dl,           srl);
        cpa16(dl + 8192u,   srl + 512);
    };
    auto issue2 = [&](int pp, int slot) {   // 8192 floats = 4 x 512 float4
        const float4* src = ((const float4*)g_Wt2) + (size_t)pp * 2048 + tid;
        unsigned int dst = wb_u32 + (unsigned int)slot * (SLOT2P * 4u) + tid * 16u;
        #pragma unroll
        for (int i = 0; i < 4; ++i)
            cpa16(dst + (unsigned int)i * 8192u, src + i * 512);
    };

    for (int t = 0; t < T_STEPS; ++t) {
        // prefetch eps for phase 2b
        float ea[2], eb[2];
        {
            const int mr = wrp * 2;
            const float* ep = eps + ((size_t)t * B_TOT + bBase + mr) * LAT;
            ea[0] = __ldg(ep + lane);        eb[0] = __ldg(ep + lane + 32);
            ea[1] = __ldg(ep + LAT + lane);  eb[1] = __ldg(ep + LAT + lane + 32);
        }

        // ======== Phase 1: gates GEMM via 3xTF32 mma, LSTM update ========
        {
            issue1(0, 0); cpa_commit();
            issue1(1, 1); cpa_commit();

            float dacc[2][8][4];
            #pragma unroll
            for (int a = 0; a < 2; ++a)
                #pragma unroll
                for (int b = 0; b < 8; ++b)
                    #pragma unroll
                    for (int c = 0; c < 4; ++c) dacc[a][b][c] = 0.f;

            for (int p = 0; p < NP1; ++p) {
                if (p + 1 < NP1) cpa_wait1(); else cpa_wait0();
                __syncthreads();     // panel p visible; slot (p+2)%3 free
                if (p + 2 < NP1) { issue1(p + 2, (p + 2) % 3); cpa_commit(); }
                const float*    wch = wbA + (p % 3) * SLOTC;
                const unsigned* wcl = (const unsigned*)(wch + 8192);
                const float* Ab = (p < 8) ? (xs + p * 8 * MS)
                                          : (hs + (p * 8 - 64) * MS);
                #pragma unroll
                for (int mt = 0; mt < 2; ++mt) {
                    // A fragment (m16 x k8) + on-the-fly hi/lo split
                    float ah[4], al[4];
                    #pragma unroll
                    for (int r = 0; r < 4; ++r) {
                        int c = ((r >> 1) << 2) + tq;          // k within chunk
                        int m = mt * 16 + qg + ((r & 1) << 3); // batch row
                        float a = Ab[c * MS + m];
                        ah[r] = tf32r(a);
                        al[r] = tf32r(a - ah[r]);
                    }
                    #pragma unroll
                    for (int nf = 0; nf < 8; ++nf) {   // nf = gate*2 + s
                        int g = nf >> 1, s = nf & 1;
                        int n = (g << 8) + wrp * 16 + (s << 3) + qg;
                        float2 BH = *((const float2*)wch + n * 4 + tq);
                        unsigned u = wcl[n * 4 + tq];
                        float2 BL;
                        BL.x = __uint_as_float(u << 16);
                        BL.y = __uint_as_float(u & 0xFFFF0000u);
                        float* D = dacc[mt][nf];
                        mma_tf32(D, ah, BH);
                        mma_tf32(D, ah, BL);
                        mma_tf32(D, al, BH);
                    }
                }
            }
            __syncthreads();         // all warps done reading hs/panels

            // epilogue: bias + LSTM nonlinearity; c in regs, h in place
            #pragma unroll
            for (int s = 0; s < 2; ++s) {
                const int j0 = wrp * 16 + (s << 3) + (tq << 1);
                const int j1 = j0 + 1;
                const float bi0 = bsum[j0],       bi1 = bsum[j1];
                const float bf0 = bsum[256 + j0], bf1 = bsum[256 + j1];
                const float bg0 = bsum[512 + j0], bg1 = bsum[512 + j1];
                const float bo0 = bsum[768 + j0], bo1 = bsum[768 + j1];
                #pragma unroll
                for (int mt = 0; mt < 2; ++mt) {
                    #pragma unroll
                    for (int rh = 0; rh < 2; ++rh) {
                        const int m = mt * 16 + qg + (rh << 3);
                        const int cb = ((((s << 1) | mt) << 1) | rh) << 1;
                        {
                            float iv = sig_f(dacc[mt][0 + s][rh * 2] + bi0);
                            float fv = sig_f(dacc[mt][2 + s][rh * 2] + bf0);
                            float gv = tanh_f(dacc[mt][4 + s][rh * 2] + bg0);
                            float ov = sig_f(dacc[mt][6 + s][rh * 2] + bo0);
                            float c = fv * c_reg[cb] + iv * gv;
                            c_reg[cb] = c;
                            hs[j0 * MS + m] = ov * tanh_f(c);
                        }
                        {
                            float iv = sig_f(dacc[mt][0 + s][rh * 2 + 1] + bi1);
                            float fv = sig_f(dacc[mt][2 + s][rh * 2 + 1] + bf1);
                            float gv = tanh_f(dacc[mt][4 + s][rh * 2 + 1] + bg1);
                            float ov = sig_f(dacc[mt][6 + s][rh * 2 + 1] + bo1);
                            float c = fv * c_reg[cb + 1] + iv * gv;
                            c_reg[cb + 1] = c;
                            hs[j1 * MS + m] = ov * tanh_f(c);
                        }
                    }
                }
            }
        }

        // ======== Phase 2a: [mu;logvar] = h @ [Wmu;Wvar]^T (FFMA2) ========
        {
            issue2(0, 0); cpa_commit();

            ull acc2[4] = {0ULL, 0ULL, 0ULL, 0ULL};

            for (int pp = 0; pp < NPP2; ++pp) {
                cpa_wait0();
                __syncthreads();     // also orders phase-1 hs epilogue writes
                if (pp + 1 < NPP2) { issue2(pp + 1, (pp + 1) & 1); cpa_commit(); }
                const float* wc = wbA + (pp & 1) * SLOT2P;
                const int k0 = pp * 64;
                #pragma unroll 16
                for (int kk = 0; kk < 64; ++kk) {
                    float4 a = *(const float4*)(hs + (k0 + kk) * MS + m08);
                    ull w = *(const ull*)(wc + kk * 128 + jq2);
                    fma2(acc2[0], pack2s(a.x), w);
                    fma2(acc2[1], pack2s(a.y), w);
                    fma2(acc2[2], pack2s(a.z), w);
                    fma2(acc2[3], pack2s(a.w), w);
                }
            }
            __syncthreads();         // all warps done with panel slots

            // epilogue: row pair (jq2, jq2+1) for 4 m rows -> mus/lvs (slot0)
            if (jq2 < 64) {
                const float b0 = bmu_s[jq2], b1 = bmu_s[jq2 + 1];
                #pragma unroll
                for (int m = 0; m < 4; ++m) {
                    float2 v = unpack2(acc2[m]);
                    mus[jq2 * MS + m08 + m]       = v.x + b0;
                    mus[(jq2 + 1) * MS + m08 + m] = v.y + b1;
                }
            } else {
                const int l0 = jq2 - 64;
                const float b0 = bvar_s[l0], b1 = bvar_s[l0 + 1];
                #pragma unroll
                for (int m = 0; m < 4; ++m) {
                    float2 v = unpack2(acc2[m]);
                    lvs[l0 * MS + m08 + m]       = v.x + b0;
                    lvs[(l0 + 1) * MS + m08 + m] = v.y + b1;
                }
            }
        }
        __syncthreads();

        // ======== Phase 2b: gen/on + reparameterized z ========
        #pragma unroll
        for (int r = 0; r < 2; ++r) {
            const int m = wrp * 2 + r;
            const int b = bBase + m;
            float gp = 0.f, op = 0.f;
            #pragma unroll
            for (int i2 = 0; i2 < 8; ++i2) {
                int k = lane + 32 * i2;
                float hv = hs[k * MS + m];
                gp = fmaf(hv, wgv[k], gp);
                op = fmaf(hv, wov[k], op);
            }
            #pragma unroll
            for (int s2 = 16; s2 > 0; s2 >>= 1) {
                gp += __shfl_xor_sync(0xffffffffu, gp, s2);
                op += __shfl_xor_sync(0xffffffffu, op, s2);
            }
            if (lane == 0) {
                float gen = fmaxf(gp + bgv, 0.f);
                float on  = (op + bov) > 0.f ? 1.f : 0.f;
                abuf[m] = gen * on;
                out[O_GENS  + (size_t)b * T_STEPS + t] = gen;
                out[O_ONOFF + (size_t)b * T_STEPS + t] = on;
            }
            float mu0 = mus[lane * MS + m],        lv0 = lvs[lane * MS + m];
            float mu1 = mus[(lane + 32) * MS + m], lv1 = lvs[(lane + 32) * MS + m];
            zs[lane * MS + m]        = ea[r] * __expf(0.5f * lv0) + mu0;
            zs[(lane + 32) * MS + m] = eb[r] * __expf(0.5f * lv1) + mu1;
        }
        __syncwarp();

        // ======== Phase 3: delta = z@Wnext^T, state update, totals ========
        #pragma unroll
        for (int r = 0; r < 2; ++r) {
            const int m = wrp * 2 + r;
            const int b = bBase + m;
            float d0 = bnx_s[lane], d1 = bnx_s[lane + 32];
            #pragma unroll 8
            for (int l = 0; l < LAT; ++l) {
                float zl = zs[l * MS + m];
                d0 = fmaf(zl, wnT[l * 64 + lane],      d0);
                d1 = fmaf(zl, wnT[l * 64 + lane + 32], d1);
            }
            float xn0 = (lane == 0) ? 0.f : fmaxf(xs[lane * MS + m] + d0, 0.f);
            float xn1 = fmaxf(xs[(lane + 32) * MS + m] + d1, 0.f);
            float part = xn0 + xn1;
            #pragma unroll
            for (int s2 = 16; s2 > 0; s2 >>= 1)
                part += __shfl_xor_sync(0xffffffffu, part, s2);
            float add = abuf[m];
            float v0 = (lane == 0) ? add : xn0;
            size_t ob = O_STATES + ((size_t)b * T_STEPS + t) * D_IN;
            out[ob + lane]      = v0;
            out[ob + lane + 32] = xn1;
            xs[lane * MS + m]        = v0;
            xs[(lane + 32) * MS + m] = xn1;
            if (lane == 0) {
                out[O_TPRE  + (size_t)b * 128 + t + 1] = part;
                out[O_TPOST + (size_t)b * 128 + t + 1] = part + add;
            }
        }
        __syncthreads();   // xs/hs stable before next step's phase 1
    }
}

extern "C" void kernel_launch(void* const* d_in, const int* in_sizes, int n_in,
                              void* d_out, int out_size) {
    const float* data  = (const float*)d_in[0];
    const float* locs  = (const float*)d_in[1];
    const float* Wih   = (const float*)d_in[2];
    const float* Whh   = (const float*)d_in[3];
    const float* bih   = (const float*)d_in[4];
    const float* bhh   = (const float*)d_in[5];
    const float* Wmu   = (const float*)d_in[6];
    const float* bmu   = (const float*)d_in[7];
    const float* Wvar  = (const float*)d_in[8];
    const float* bvar  = (const float*)d_in[9];
    const float* Wvelo = (const float*)d_in[10];
    const float* bvelo = (const float*)d_in[11];
    const float* Wsw   = (const float*)d_in[12];
    const float* bsw   = (const float*)d_in[13];
    const float* Wgen  = (const float*)d_in[14];
    const float* bgen  = (const float*)d_in[15];
    const float* Won   = (const float*)d_in[16];
    const float* bon   = (const float*)d_in[17];
    const float* Wnext = (const float*)d_in[18];
    const float* bnext = (const float*)d_in[19];
    const float* Wloc  = (const float*)d_in[20];
    const float* bloc  = (const float*)d_in[21];
    const float* eps   = (const float*)d_in[22];
    float* out = (float*)d_out;

    prep_all_kernel<<<256, 512>>>(Wih, Whh, Wmu, Wvar,
                                  Wgen, bgen, Won, bon,
                                  Wvelo, bvelo, Wsw, bsw);

    // floats: 19680 (state) + 3 * 12288 (panel slots) = 56544
    const size_t smem_bytes = 56544 * sizeof(float);  // 226,176 B
    cudaFuncSetAttribute(model_kernel,
                         cudaFuncAttributeMaxDynamicSharedMemorySize,
                         (int)smem_bytes);
    model_kernel<<<NCTA, NTH, smem_bytes>>>(data, locs, bih, bhh,
                                            bmu, bvar, Wnext, bnext,
                                            Wloc, bloc, eps, out);
}